// round 1
// baseline (speedup 1.0000x reference)
#include <cuda_runtime.h>
#include <math.h>

#define PTS 64
#define HD  20
#define KNN 4

// ---- shared weight blob offsets (floats) ----
#define O_WI0 0
#define O_BI0 60
#define O_WI1 80
#define O_BI1 480
#define O_WI2 500
#define O_BI2 900
#define O_WA0 920
#define O_BA0 1720
#define O_WB0 1740
#define O_BB0 2140
#define O_WA1 2160
#define O_BA1 2960
#define O_WB1 2980
#define O_BB1 3380
#define O_WO0 3400
#define O_BO0 3800
#define O_WO1 3820
#define O_BO1 4220
#define O_WO2 4240
#define O_BO2 4440
#define W_TOTAL 4450

__device__ __forceinline__ float eluf(float v) {
    return v > 0.f ? v : expm1f(v);
}

// order-preserving float -> uint mapping (monotone for all finite + inf values)
__device__ __forceinline__ unsigned ordf(float f) {
    unsigned u = __float_as_uint(f);
    return (u & 0x80000000u) ? ~u : (u | 0x80000000u);
}

// acc[0..19] += f * W[0..19], W row is 16B-aligned shared memory
__device__ __forceinline__ void fma_row20(const float* Wrow, float f, float* acc) {
    const float4* w4 = reinterpret_cast<const float4*>(Wrow);
#pragma unroll
    for (int q = 0; q < 5; ++q) {
        float4 w = w4[q];
        acc[4 * q + 0] = fmaf(f, w.x, acc[4 * q + 0]);
        acc[4 * q + 1] = fmaf(f, w.y, acc[4 * q + 1]);
        acc[4 * q + 2] = fmaf(f, w.z, acc[4 * q + 2]);
        acc[4 * q + 3] = fmaf(f, w.w, acc[4 * q + 3]);
    }
}

// 20->20 dense: in (shared row of 20), W (20x20 row-major in shared), acc in regs
__device__ __forceinline__ void dense20(const float* W, const float* bias,
                                        const float* in, float* acc) {
#pragma unroll
    for (int d = 0; d < HD; ++d) acc[d] = bias[d];
#pragma unroll 1
    for (int e = 0; e < HD; ++e) fma_row20(W + e * HD, in[e], acc);
}

__global__ __launch_bounds__(PTS)
void net_kernel(const float* __restrict__ x,
                const float* __restrict__ Wi0, const float* __restrict__ bi0,
                const float* __restrict__ Wi1, const float* __restrict__ bi1,
                const float* __restrict__ Wi2, const float* __restrict__ bi2,
                const float* __restrict__ Wa0, const float* __restrict__ ba0,
                const float* __restrict__ Wb0, const float* __restrict__ bb0,
                const float* __restrict__ Wa1, const float* __restrict__ ba1,
                const float* __restrict__ Wb1, const float* __restrict__ bb1,
                const float* __restrict__ Wo0, const float* __restrict__ bo0,
                const float* __restrict__ Wo1, const float* __restrict__ bo1,
                const float* __restrict__ Wo2, const float* __restrict__ bo2,
                float* __restrict__ out) {
    __shared__ float sW[W_TOTAL];
    __shared__ __align__(16) float sh[PTS][HD];   // current point features
    __shared__ __align__(16) float st[PTS][HD];   // scratch / edgeconv output
    __shared__ float ssq[PTS];
    __shared__ int   svalid[PTS];
    __shared__ int   sc[PTS];
    __shared__ float sg[HD];
    __shared__ float sg2[HD];
    __shared__ float slog[10];
    __shared__ float slse;

    const int tid = threadIdx.x;  // point id, 0..63
    const int b = blockIdx.x;

    // ---- stage all weights into shared ----
    {
        const float* srcs[20] = {Wi0, bi0, Wi1, bi1, Wi2, bi2,
                                 Wa0, ba0, Wb0, bb0, Wa1, ba1, Wb1, bb1,
                                 Wo0, bo0, Wo1, bo1, Wo2, bo2};
        const int offs[21] = {O_WI0, O_BI0, O_WI1, O_BI1, O_WI2, O_BI2,
                              O_WA0, O_BA0, O_WB0, O_BB0, O_WA1, O_BA1,
                              O_WB1, O_BB1, O_WO0, O_BO0, O_WO1, O_BO1,
                              O_WO2, O_BO2, W_TOTAL};
        for (int a = 0; a < 20; ++a) {
            int n = offs[a + 1] - offs[a];
            const float* s = srcs[a];
            float* dptr = sW + offs[a];
            for (int t = tid; t < n; t += PTS) dptr[t] = s[t];
        }
    }
    svalid[tid] = 1;
    __syncthreads();

    // ---- input MLP: 3 -> 20 -> 20 -> 20 ----
    {
        const float x0 = x[(b * PTS + tid) * 3 + 0];
        const float x1 = x[(b * PTS + tid) * 3 + 1];
        const float x2 = x[(b * PTS + tid) * 3 + 2];
        float a[HD];
#pragma unroll
        for (int d = 0; d < HD; ++d) {
            float v = sW[O_BI0 + d];
            v = fmaf(x0, sW[O_WI0 + 0 * HD + d], v);
            v = fmaf(x1, sW[O_WI0 + 1 * HD + d], v);
            v = fmaf(x2, sW[O_WI0 + 2 * HD + d], v);
            a[d] = eluf(v);
        }
#pragma unroll
        for (int d = 0; d < HD; ++d) st[tid][d] = a[d];
        dense20(sW + O_WI1, sW + O_BI1, &st[tid][0], a);
#pragma unroll
        for (int d = 0; d < HD; ++d) st[tid][d] = eluf(a[d]);
        dense20(sW + O_WI2, sW + O_BI2, &st[tid][0], a);
#pragma unroll
        for (int d = 0; d < HD; ++d) sh[tid][d] = eluf(a[d]);
    }

    // ---- two EdgeConv + pool rounds ----
#pragma unroll 1
    for (int r = 0; r < 2; ++r) {
        const float* Wa = sW + (r ? O_WA1 : O_WA0);
        const float* ba = sW + (r ? O_BA1 : O_BA0);
        const float* Wb = sW + (r ? O_WB1 : O_WB0);
        const float* bb = sW + (r ? O_BB1 : O_BB0);

        // own row -> regs, squared norm
        float hi[HD];
#pragma unroll
        for (int q = 0; q < 5; ++q) {
            float4 v = *reinterpret_cast<const float4*>(&sh[tid][4 * q]);
            hi[4 * q + 0] = v.x; hi[4 * q + 1] = v.y;
            hi[4 * q + 2] = v.z; hi[4 * q + 3] = v.w;
        }
        float sq = 0.f;
#pragma unroll
        for (int d = 0; d < HD; ++d) sq = fmaf(hi[d], hi[d], sq);
        ssq[tid] = sq;
        __syncthreads();  // sh, svalid, ssq of all points visible

        // ---- KNN: top-4 by score = 2*dot - sq_i - sq_j (stable tie-break: lower j) ----
        unsigned long long k0 = 0ull, k1 = 0ull, k2 = 0ull, k3 = 0ull;
#pragma unroll 1
        for (int j = 0; j < PTS; ++j) {
            float s;
            if (j == tid || !svalid[j]) {
                s = -INFINITY;
            } else {
                float d0 = 0.f, d1 = 0.f, d2 = 0.f, d3 = 0.f;
#pragma unroll
                for (int q = 0; q < 5; ++q) {
                    float4 hj = *reinterpret_cast<const float4*>(&sh[j][4 * q]);
                    d0 = fmaf(hi[4 * q + 0], hj.x, d0);
                    d1 = fmaf(hi[4 * q + 1], hj.y, d1);
                    d2 = fmaf(hi[4 * q + 2], hj.z, d2);
                    d3 = fmaf(hi[4 * q + 3], hj.w, d3);
                }
                s = 2.f * ((d0 + d1) + (d2 + d3)) - sq - ssq[j];
            }
            unsigned long long key =
                ((unsigned long long)ordf(s) << 32) | (unsigned)(PTS - 1 - j);
            if (key > k0)      { k3 = k2; k2 = k1; k1 = k0; k0 = key; }
            else if (key > k1) { k3 = k2; k2 = k1; k1 = key; }
            else if (key > k2) { k3 = k2; k2 = key; }
            else if (key > k3) { k3 = key; }
        }
        int njs[4];
        njs[0] = PTS - 1 - (int)(k0 & 0xFFFFFFFFull);
        njs[1] = PTS - 1 - (int)(k1 & 0xFFFFFFFFull);
        njs[2] = PTS - 1 - (int)(k2 & 0xFFFFFFFFull);
        njs[3] = PTS - 1 - (int)(k3 & 0xFFFFFFFFull);

        // ---- EdgeConv: sum_k elu(elu([xi, xj-xi] @ Wa + ba) @ Wb + bb) * valid_j ----
        float acc[HD];
#pragma unroll
        for (int d = 0; d < HD; ++d) acc[d] = 0.f;

#pragma unroll 1
        for (int k = 0; k < KNN; ++k) {
            const int j = njs[k];
            const float fj = (float)svalid[j];
            const float* hjrow = &sh[j][0];
            float m[HD];
#pragma unroll
            for (int d = 0; d < HD; ++d) m[d] = ba[d];
            // first 20 features: xi
#pragma unroll 1
            for (int e = 0; e < HD; ++e) fma_row20(Wa + e * HD, hi[e], m);
            // next 20 features: xj - xi
#pragma unroll 1
            for (int e = 0; e < HD; ++e)
                fma_row20(Wa + (HD + e) * HD, hjrow[e] - hi[e], m);
#pragma unroll
            for (int d = 0; d < HD; ++d) st[tid][d] = eluf(m[d]);  // scratch m1
            float m2[HD];
            dense20(Wb, bb, &st[tid][0], m2);
#pragma unroll
            for (int d = 0; d < HD; ++d) acc[d] = fmaf(eluf(m2[d]), fj, acc[d]);
        }

        const float mv = (float)svalid[tid];
#pragma unroll
        for (int d = 0; d < HD; ++d) st[tid][d] = acc[d] * mv;
        sc[tid] = svalid[tid] ? min(tid, njs[0]) : PTS;
        __syncthreads();  // st (edgeconv out) and sc visible to all

        // ---- pool: thread tid owns cluster slot tid ----
        float pm[HD];
#pragma unroll
        for (int d = 0; d < HD; ++d) pm[d] = -INFINITY;
        int pcnt = 0;
#pragma unroll 1
        for (int j = 0; j < PTS; ++j) {
            if (sc[j] == tid) {
                ++pcnt;
#pragma unroll
                for (int q = 0; q < 5; ++q) {
                    float4 v = *reinterpret_cast<const float4*>(&st[j][4 * q]);
                    pm[4 * q + 0] = fmaxf(pm[4 * q + 0], v.x);
                    pm[4 * q + 1] = fmaxf(pm[4 * q + 1], v.y);
                    pm[4 * q + 2] = fmaxf(pm[4 * q + 2], v.z);
                    pm[4 * q + 3] = fmaxf(pm[4 * q + 3], v.w);
                }
            }
        }
        const int nv = (pcnt > 0);
        svalid[tid] = nv;
#pragma unroll
        for (int d = 0; d < HD; ++d) sh[tid][d] = nv ? pm[d] : 0.f;
        // next-round top sync (or final sync below) publishes sh/svalid
        __syncthreads();
    }

    // ---- global max over valid points ----
    if (tid < HD) {
        float g = -INFINITY;
#pragma unroll 1
        for (int j = 0; j < PTS; ++j)
            if (svalid[j]) g = fmaxf(g, sh[j][tid]);
        sg[tid] = g;
    }
    __syncthreads();

    // ---- output MLP: 20 -> 20 -> 20 -> 10, log-softmax ----
    if (tid < HD) {
        float a = sW[O_BO0 + tid];
#pragma unroll 1
        for (int e = 0; e < HD; ++e) a = fmaf(sg[e], sW[O_WO0 + e * HD + tid], a);
        sg2[tid] = eluf(a);
    }
    __syncthreads();
    if (tid < HD) {
        float a = sW[O_BO1 + tid];
#pragma unroll 1
        for (int e = 0; e < HD; ++e) a = fmaf(sg2[e], sW[O_WO1 + e * HD + tid], a);
        sg[tid] = eluf(a);
    }
    __syncthreads();
    if (tid < 10) {
        float a = sW[O_BO2 + tid];
#pragma unroll 1
        for (int e = 0; e < HD; ++e) a = fmaf(sg[e], sW[O_WO2 + e * 10 + tid], a);
        slog[tid] = a;
    }
    __syncthreads();
    if (tid == 0) {
        float mx = slog[0];
#pragma unroll
        for (int i = 1; i < 10; ++i) mx = fmaxf(mx, slog[i]);
        float ssum = 0.f;
#pragma unroll
        for (int i = 0; i < 10; ++i) ssum += expf(slog[i] - mx);
        slse = mx + logf(ssum);
    }
    __syncthreads();
    if (tid < 10) out[b * 10 + tid] = slog[tid] - slse;
}

extern "C" void kernel_launch(void* const* d_in, const int* in_sizes, int n_in,
                              void* d_out, int out_size) {
    const float* x = (const float*)d_in[0];
    const int B = in_sizes[0] / (PTS * 3);
    net_kernel<<<B, PTS>>>(
        x,
        (const float*)d_in[1],  (const float*)d_in[2],
        (const float*)d_in[3],  (const float*)d_in[4],
        (const float*)d_in[5],  (const float*)d_in[6],
        (const float*)d_in[7],  (const float*)d_in[8],
        (const float*)d_in[9],  (const float*)d_in[10],
        (const float*)d_in[11], (const float*)d_in[12],
        (const float*)d_in[13], (const float*)d_in[14],
        (const float*)d_in[15], (const float*)d_in[16],
        (const float*)d_in[17], (const float*)d_in[18],
        (const float*)d_in[19], (const float*)d_in[20],
        (float*)d_out);
}

// round 2
// speedup vs baseline: 3.4576x; 3.4576x over previous
#include <cuda_runtime.h>
#include <math.h>

#define PTS 64
#define HD  20

typedef unsigned long long u64;

// per-round edgeconv weight blob (floats)
#define E_WA 0
#define E_BA 800
#define E_WB 820
#define E_BB 1220
#define E_TOT 1240
// input-MLP blob (floats), staged into same sW
#define I_W0 0
#define I_B0 60
#define I_W1 80
#define I_B1 480
#define I_W2 500
#define I_B2 900

__device__ __forceinline__ u64 pk2(float a, float b) {
    u64 r; asm("mov.b64 %0, {%1, %2};" : "=l"(r) : "f"(a), "f"(b)); return r;
}
__device__ __forceinline__ void up2(u64 v, float& a, float& b) {
    asm("mov.b64 {%0, %1}, %2;" : "=f"(a), "=f"(b) : "l"(v));
}
__device__ __forceinline__ u64 splat2(float f) { return pk2(f, f); }
__device__ __forceinline__ u64 fma2v(u64 a, u64 b, u64 c) {
    u64 d; asm("fma.rn.f32x2 %0, %1, %2, %3;" : "=l"(d) : "l"(a), "l"(b), "l"(c)); return d;
}
__device__ __forceinline__ float eluf(float v) { return v > 0.f ? v : (__expf(v) - 1.0f); }

__device__ __forceinline__ void stage(float* dst, const float* __restrict__ src,
                                      int n, int tid) {
    for (int t = tid; t < n; t += PTS) dst[t] = src[t];
}

// 20->20 dense on packed pairs; input/output in h regs (e-loop fully unrolled),
// weights/bias rows 16B-aligned in shared. Applies ELU to output.
__device__ __forceinline__ void dense20p(const float* W, const float* bias, float* h) {
    u64 o[10];
    const ulonglong2* bp = reinterpret_cast<const ulonglong2*>(bias);
#pragma unroll
    for (int q = 0; q < 5; ++q) { ulonglong2 v = bp[q]; o[2 * q] = v.x; o[2 * q + 1] = v.y; }
#pragma unroll
    for (int e = 0; e < HD; ++e) {
        u64 f = splat2(h[e]);
        const ulonglong2* wp = reinterpret_cast<const ulonglong2*>(W + e * HD);
#pragma unroll
        for (int q = 0; q < 5; ++q) {
            ulonglong2 w = wp[q];
            o[2 * q]     = fma2v(f, w.x, o[2 * q]);
            o[2 * q + 1] = fma2v(f, w.y, o[2 * q + 1]);
        }
    }
#pragma unroll
    for (int q = 0; q < 10; ++q) {
        float a, bv; up2(o[q], a, bv);
        h[2 * q] = eluf(a); h[2 * q + 1] = eluf(bv);
    }
}

__global__ __launch_bounds__(PTS, 8)
void net_kernel(const float* __restrict__ x,
                const float* __restrict__ Wi0, const float* __restrict__ bi0,
                const float* __restrict__ Wi1, const float* __restrict__ bi1,
                const float* __restrict__ Wi2, const float* __restrict__ bi2,
                const float* __restrict__ Wa0, const float* __restrict__ ba0,
                const float* __restrict__ Wb0, const float* __restrict__ bb0,
                const float* __restrict__ Wa1, const float* __restrict__ ba1,
                const float* __restrict__ Wb1, const float* __restrict__ bb1,
                const float* __restrict__ Wo0, const float* __restrict__ bo0,
                const float* __restrict__ Wo1, const float* __restrict__ bo1,
                const float* __restrict__ Wo2, const float* __restrict__ bo2,
                float* __restrict__ out) {
    __shared__ __align__(16) float sW[E_TOT];
    __shared__ __align__(16) float sh[PTS][HD];
    __shared__ float sa[PTS][21];   // scratch: elu(m1) for neighbor A (stride 21: conflict-free)
    __shared__ float sb[PTS][21];   // scratch: elu(m1) for neighbor B
    __shared__ float ssq[PTS];
    __shared__ float sval[PTS];
    __shared__ int   sc[PTS];
    __shared__ float sg[HD], sg2[HD], slog[10];
    __shared__ float slse;

    const int tid = threadIdx.x;
    const int b = blockIdx.x;

    // early global loads
    const float x0 = x[(b * PTS + tid) * 3 + 0];
    const float x1 = x[(b * PTS + tid) * 3 + 1];
    const float x2 = x[(b * PTS + tid) * 3 + 2];

    // ---- stage input-MLP weights ----
    stage(sW + I_W0, Wi0, 60, tid);
    stage(sW + I_B0, bi0, HD, tid);
    stage(sW + I_W1, Wi1, 400, tid);
    stage(sW + I_B1, bi1, HD, tid);
    stage(sW + I_W2, Wi2, 400, tid);
    stage(sW + I_B2, bi2, HD, tid);
    sval[tid] = 1.f;
    __syncthreads();

    // ---- input MLP: 3 -> 20 -> 20 -> 20, result in h regs ----
    float h[HD];
#pragma unroll
    for (int d = 0; d < HD; ++d) {
        float v = sW[I_B0 + d];
        v = fmaf(x0, sW[I_W0 + 0 * HD + d], v);
        v = fmaf(x1, sW[I_W0 + 1 * HD + d], v);
        v = fmaf(x2, sW[I_W0 + 2 * HD + d], v);
        h[d] = eluf(v);
    }
    dense20p(sW + I_W1, sW + I_B1, h);
    dense20p(sW + I_W2, sW + I_B2, h);

    bool myvalid = true;

    // ---- two EdgeConv + pool rounds ----
#pragma unroll 1
    for (int r = 0; r < 2; ++r) {
        __syncthreads();  // previous readers of sW / sh are done
        stage(sW + E_WA, r ? Wa1 : Wa0, 800, tid);
        stage(sW + E_BA, r ? ba1 : ba0, HD, tid);
        stage(sW + E_WB, r ? Wb1 : Wb0, 400, tid);
        stage(sW + E_BB, r ? bb1 : bb0, HD, tid);

        // publish h (packed) + ssq (+INF marks invalid)
#pragma unroll
        for (int q = 0; q < 5; ++q)
            reinterpret_cast<float4*>(&sh[tid][0])[q] =
                make_float4(h[4 * q], h[4 * q + 1], h[4 * q + 2], h[4 * q + 3]);
        float sq = 0.f;
#pragma unroll
        for (int d = 0; d < HD; ++d) sq = fmaf(h[d], h[d], sq);
        ssq[tid] = myvalid ? sq : INFINITY;
        __syncthreads();

        // ---- KNN top-4 (stable: strict '>' keeps earliest index on ties) ----
        u64 hi2[10];
#pragma unroll
        for (int q = 0; q < 10; ++q) hi2[q] = pk2(h[2 * q], h[2 * q + 1]);
        float s0 = -INFINITY, s1 = -INFINITY, s2 = -INFINITY, s3 = -INFINITY;
        int i0 = 0, i1 = 1, i2 = 2, i3 = 3;
#pragma unroll 2
        for (int j = 0; j < PTS; ++j) {
            const ulonglong2* hp = reinterpret_cast<const ulonglong2*>(&sh[j][0]);
            u64 pa = 0ull, pb = 0ull;
#pragma unroll
            for (int q = 0; q < 5; ++q) {
                ulonglong2 w = hp[q];
                pa = fma2v(hi2[2 * q], w.x, pa);
                pb = fma2v(hi2[2 * q + 1], w.y, pb);
            }
            float fa, fb, fc, fd; up2(pa, fa, fb); up2(pb, fc, fd);
            float dot = (fa + fc) + (fb + fd);   // = (d0+d1)+(d2+d3) grouping
            float s = 2.f * dot - sq - ssq[j];
            s = (j == tid) ? -INFINITY : s;
            if (s > s0)      { s3 = s2; i3 = i2; s2 = s1; i2 = i1; s1 = s0; i1 = i0; s0 = s; i0 = j; }
            else if (s > s1) { s3 = s2; i3 = i2; s2 = s1; i2 = i1; s1 = s; i1 = j; }
            else if (s > s2) { s3 = s2; i3 = i2; s2 = s; i2 = j; }
            else if (s > s3) { s3 = s; i3 = j; }
        }

        // ---- EdgeConv ----
        // u = ba + Wa_top^T * h   (neighbor-independent; exact same summation order)
        u64 u[10];
        {
            const ulonglong2* bp = reinterpret_cast<const ulonglong2*>(sW + E_BA);
#pragma unroll
            for (int q = 0; q < 5; ++q) { ulonglong2 v = bp[q]; u[2 * q] = v.x; u[2 * q + 1] = v.y; }
#pragma unroll
            for (int e = 0; e < HD; ++e) {
                u64 f = splat2(h[e]);
                const ulonglong2* wp = reinterpret_cast<const ulonglong2*>(sW + E_WA + e * HD);
#pragma unroll
                for (int q = 0; q < 5; ++q) {
                    ulonglong2 w = wp[q];
                    u[2 * q]     = fma2v(f, w.x, u[2 * q]);
                    u[2 * q + 1] = fma2v(f, w.y, u[2 * q + 1]);
                }
            }
        }

        float acc[HD];
#pragma unroll
        for (int d = 0; d < HD; ++d) acc[d] = 0.f;

        auto do_pass = [&](int j0, int j1) {
            u64 m0[10], m1[10];
#pragma unroll
            for (int q = 0; q < 10; ++q) { m0[q] = u[q]; m1[q] = u[q]; }
            // layer1 bottom half for 2 neighbors sharing weight-row loads
#pragma unroll 2
            for (int e = 0; e < HD; ++e) {
                float he = sh[tid][e];
                u64 d0 = splat2(sh[j0][e] - he);
                u64 d1 = splat2(sh[j1][e] - he);
                const ulonglong2* wp =
                    reinterpret_cast<const ulonglong2*>(sW + E_WA + (HD + e) * HD);
#pragma unroll
                for (int q = 0; q < 5; ++q) {
                    ulonglong2 w = wp[q];
                    m0[2 * q]     = fma2v(d0, w.x, m0[2 * q]);
                    m0[2 * q + 1] = fma2v(d0, w.y, m0[2 * q + 1]);
                    m1[2 * q]     = fma2v(d1, w.x, m1[2 * q]);
                    m1[2 * q + 1] = fma2v(d1, w.y, m1[2 * q + 1]);
                }
            }
            // elu -> per-thread scratch (conflict-free stride 21)
#pragma unroll
            for (int q = 0; q < 10; ++q) {
                float va, vb;
                up2(m0[q], va, vb);
                sa[tid][2 * q] = eluf(va); sa[tid][2 * q + 1] = eluf(vb);
                up2(m1[q], va, vb);
                sb[tid][2 * q] = eluf(va); sb[tid][2 * q + 1] = eluf(vb);
            }
            // layer2 for both neighbors
            u64 n0[10], n1[10];
            {
                const ulonglong2* bp = reinterpret_cast<const ulonglong2*>(sW + E_BB);
#pragma unroll
                for (int q = 0; q < 5; ++q) {
                    ulonglong2 v = bp[q];
                    n0[2 * q] = v.x; n0[2 * q + 1] = v.y;
                    n1[2 * q] = v.x; n1[2 * q + 1] = v.y;
                }
            }
#pragma unroll 2
            for (int e = 0; e < HD; ++e) {
                u64 f0 = splat2(sa[tid][e]);
                u64 f1 = splat2(sb[tid][e]);
                const ulonglong2* wp =
                    reinterpret_cast<const ulonglong2*>(sW + E_WB + e * HD);
#pragma unroll
                for (int q = 0; q < 5; ++q) {
                    ulonglong2 w = wp[q];
                    n0[2 * q]     = fma2v(f0, w.x, n0[2 * q]);
                    n0[2 * q + 1] = fma2v(f0, w.y, n0[2 * q + 1]);
                    n1[2 * q]     = fma2v(f1, w.x, n1[2 * q]);
                    n1[2 * q + 1] = fma2v(f1, w.y, n1[2 * q + 1]);
                }
            }
            // elu + masked accumulate (neighbor order preserved: j0 then j1)
            const float fj0 = sval[j0];
            const float fj1 = sval[j1];
#pragma unroll
            for (int q = 0; q < 10; ++q) {
                float va, vb;
                up2(n0[q], va, vb);
                acc[2 * q]     = fmaf(eluf(va), fj0, acc[2 * q]);
                acc[2 * q + 1] = fmaf(eluf(vb), fj0, acc[2 * q + 1]);
                up2(n1[q], va, vb);
                acc[2 * q]     = fmaf(eluf(va), fj1, acc[2 * q]);
                acc[2 * q + 1] = fmaf(eluf(vb), fj1, acc[2 * q + 1]);
            }
        };
        do_pass(i0, i1);
        do_pass(i2, i3);

        const float mv = myvalid ? 1.f : 0.f;
        __syncthreads();   // everyone done reading sh (KNN + edgeconv)
        // reuse sh for edgeconv output
#pragma unroll
        for (int q = 0; q < 5; ++q)
            reinterpret_cast<float4*>(&sh[tid][0])[q] =
                make_float4(acc[4 * q] * mv, acc[4 * q + 1] * mv,
                            acc[4 * q + 2] * mv, acc[4 * q + 3] * mv);
        sc[tid] = myvalid ? min(tid, i0) : PTS;
        __syncthreads();

        // ---- pool: thread tid owns cluster slot tid ----
        float pm[HD];
#pragma unroll
        for (int d = 0; d < HD; ++d) pm[d] = -INFINITY;
        int pcnt = 0;
#pragma unroll 1
        for (int j = 0; j < PTS; ++j) {
            if (sc[j] == tid) {
                ++pcnt;
#pragma unroll
                for (int q = 0; q < 5; ++q) {
                    float4 v = reinterpret_cast<const float4*>(&sh[j][0])[q];
                    pm[4 * q + 0] = fmaxf(pm[4 * q + 0], v.x);
                    pm[4 * q + 1] = fmaxf(pm[4 * q + 1], v.y);
                    pm[4 * q + 2] = fmaxf(pm[4 * q + 2], v.z);
                    pm[4 * q + 3] = fmaxf(pm[4 * q + 3], v.w);
                }
            }
        }
        myvalid = (pcnt > 0);
        sval[tid] = myvalid ? 1.f : 0.f;
#pragma unroll
        for (int d = 0; d < HD; ++d) h[d] = myvalid ? pm[d] : 0.f;
    }

    // ---- global max over valid points ----
    __syncthreads();   // pool readers of sh are done
#pragma unroll
    for (int d = 0; d < HD; ++d) sh[tid][d] = myvalid ? h[d] : -INFINITY;
    __syncthreads();
    if (tid < HD) {
        float g = -INFINITY;
#pragma unroll 1
        for (int j = 0; j < PTS; ++j) g = fmaxf(g, sh[j][tid]);
        sg[tid] = g;
    }
    __syncthreads();

    // ---- output MLP (weights straight from L2) ----
    if (tid < HD) {
        float a = bo0[tid];
#pragma unroll 1
        for (int e = 0; e < HD; ++e) a = fmaf(sg[e], Wo0[e * HD + tid], a);
        sg2[tid] = eluf(a);
    }
    __syncthreads();
    if (tid < HD) {
        float a = bo1[tid];
#pragma unroll 1
        for (int e = 0; e < HD; ++e) a = fmaf(sg2[e], Wo1[e * HD + tid], a);
        sg[tid] = eluf(a);
    }
    __syncthreads();
    if (tid < 10) {
        float a = bo2[tid];
#pragma unroll 1
        for (int e = 0; e < HD; ++e) a = fmaf(sg[e], Wo2[e * 10 + tid], a);
        slog[tid] = a;
    }
    __syncthreads();
    if (tid == 0) {
        float mx = slog[0];
#pragma unroll
        for (int i = 1; i < 10; ++i) mx = fmaxf(mx, slog[i]);
        float ssum = 0.f;
#pragma unroll
        for (int i = 0; i < 10; ++i) ssum += expf(slog[i] - mx);
        slse = mx + logf(ssum);
    }
    __syncthreads();
    if (tid < 10) out[b * 10 + tid] = slog[tid] - slse;
}

extern "C" void kernel_launch(void* const* d_in, const int* in_sizes, int n_in,
                              void* d_out, int out_size) {
    const float* x = (const float*)d_in[0];
    const int B = in_sizes[0] / (PTS * 3);
    net_kernel<<<B, PTS>>>(
        x,
        (const float*)d_in[1],  (const float*)d_in[2],
        (const float*)d_in[3],  (const float*)d_in[4],
        (const float*)d_in[5],  (const float*)d_in[6],
        (const float*)d_in[7],  (const float*)d_in[8],
        (const float*)d_in[9],  (const float*)d_in[10],
        (const float*)d_in[11], (const float*)d_in[12],
        (const float*)d_in[13], (const float*)d_in[14],
        (const float*)d_in[15], (const float*)d_in[16],
        (const float*)d_in[17], (const float*)d_in[18],
        (const float*)d_in[19], (const float*)d_in[20],
        (float*)d_out);
}